// round 1
// baseline (speedup 1.0000x reference)
#include <cuda_runtime.h>

#define N 2048
#define E 4
#define C 4
#define F 128      // W_OUT
#define WIN 256

// ---------------- scratch (static device globals; no allocation) ----------------
__device__ float g_fw[3][16];          // softmaxed weights: [0]=fw1, [1]=fw2, [2]=fw3
__device__ float g_support[N * F];     // X @ gcn_w
__device__ float g_r[E * N];           // rowsums of A_i
__device__ float g_v1[C * N];          // Hc @ 1
__device__ float g_v2[C * N];          // Hb @ v1
__device__ float g_v3[C * N];          // Ha @ v2
__device__ float g_d[C * N];           // deg^-1/2
__device__ float g_Sp[C * N * F];      // diag(d) @ support
__device__ float g_T0[C * N * F];
__device__ float g_T1[C * N * F];

// ---------------- tiny: softmax of 4x4 weight rows ----------------
__global__ void k_softmax(const float* __restrict__ w1,
                          const float* __restrict__ w2,
                          const float* __restrict__ w3) {
    int t = threadIdx.x;
    if (t >= 12) return;
    int mat = t >> 2, row = t & 3;
    const float* src = (mat == 0) ? w1 : (mat == 1) ? w2 : w3;
    float a0 = src[row * 4 + 0], a1 = src[row * 4 + 1];
    float a2 = src[row * 4 + 2], a3 = src[row * 4 + 3];
    float mx = fmaxf(fmaxf(a0, a1), fmaxf(a2, a3));
    float e0 = expf(a0 - mx), e1 = expf(a1 - mx), e2 = expf(a2 - mx), e3 = expf(a3 - mx);
    float inv = 1.0f / (e0 + e1 + e2 + e3);
    g_fw[mat][row * 4 + 0] = e0 * inv;
    g_fw[mat][row * 4 + 1] = e1 * inv;
    g_fw[mat][row * 4 + 2] = e2 * inv;
    g_fw[mat][row * 4 + 3] = e3 * inv;
}

// ---------------- support = X @ gcn_w ----------------
// grid: 64 blocks (32 rows each), 256 threads
__global__ void __launch_bounds__(256) k_support(const float* __restrict__ X,
                                                 const float* __restrict__ W) {
    __shared__ float Xs[32][WIN];   // 32 KB
    int tid = threadIdx.x;
    int row0 = blockIdx.x * 32;
    const float4* Xg = (const float4*)(X + (size_t)row0 * WIN);
    float4* Xs4 = (float4*)&Xs[0][0];
    #pragma unroll
    for (int j = 0; j < (32 * WIN / 4) / 256; j++)
        Xs4[tid + j * 256] = Xg[tid + j * 256];
    __syncthreads();
    int f = tid & 127, ty = tid >> 7;  // ty in {0,1}, 16 rows each
    float acc[16];
    #pragma unroll
    for (int r = 0; r < 16; r++) acc[r] = 0.f;
    for (int k = 0; k < WIN; k++) {
        float w = W[k * F + f];
        #pragma unroll
        for (int r = 0; r < 16; r++)
            acc[r] = fmaf(Xs[ty * 16 + r][k], w, acc[r]);
    }
    #pragma unroll
    for (int r = 0; r < 16; r++)
        g_support[(size_t)(row0 + ty * 16 + r) * F + f] = acc[r];
}

// ---------------- rowsums of A_i ----------------
// grid: E*N blocks, 256 threads; block b handles flat row b of A (i = b/N, n = b%N)
__global__ void __launch_bounds__(256) k_rowsum(const float* __restrict__ A) {
    int row = blockIdx.x;
    const float4* a = (const float4*)(A + (size_t)row * N);
    int tid = threadIdx.x;
    float s = 0.f;
    #pragma unroll
    for (int it = 0; it < (N / 4) / 256; it++) {
        float4 v = a[tid + it * 256];
        s += v.x + v.y + v.z + v.w;
    }
    #pragma unroll
    for (int off = 16; off > 0; off >>= 1)
        s += __shfl_down_sync(0xffffffffu, s, off);
    __shared__ float red[8];
    int lane = tid & 31, wid = tid >> 5;
    if (lane == 0) red[wid] = s;
    __syncthreads();
    if (tid == 0) {
        float t = 0.f;
        #pragma unroll
        for (int w = 0; w < 8; w++) t += red[w];
        g_r[row] = t;
    }
}

// ---------------- v1_c = sum_i fw3[c,i] * r_i ----------------
__global__ void k_mix_v1() {
    int n = blockIdx.x * 256 + threadIdx.x;
    if (n >= N) return;
    float r0 = g_r[0 * N + n], r1 = g_r[1 * N + n];
    float r2 = g_r[2 * N + n], r3 = g_r[3 * N + n];
    #pragma unroll
    for (int c = 0; c < 4; c++) {
        g_v1[c * N + n] = g_fw[2][c * 4 + 0] * r0 + g_fw[2][c * 4 + 1] * r1
                        + g_fw[2][c * 4 + 2] * r2 + g_fw[2][c * 4 + 3] * r3;
    }
}

// ---------------- vout_c = sum_i w[c,i] * (A_i @ vin_c) ----------------
// stage 0: vin=g_v1, vout=g_v2, w=fw2 ; stage 1: vin=g_v2, vout=g_v3, w=fw1
// grid: N blocks (one row), 256 threads
__global__ void __launch_bounds__(256) k_matvec(const float* __restrict__ A, int stage) {
    const float* __restrict__ vin = (stage == 0) ? g_v1 : g_v2;
    float* __restrict__ vout = (stage == 0) ? g_v2 : g_v3;
    const float* wsrc = (stage == 0) ? g_fw[1] : g_fw[0];
    int n = blockIdx.x;
    int tid = threadIdx.x;
    float w[16];
    #pragma unroll
    for (int j = 0; j < 16; j++) w[j] = wsrc[j];
    float acc0 = 0.f, acc1 = 0.f, acc2 = 0.f, acc3 = 0.f;
    const size_t NN = (size_t)N * N;
    #pragma unroll
    for (int it = 0; it < (N / 4) / 256; it++) {
        int m4 = tid + it * 256;
        float4 vv0 = ((const float4*)(vin + 0 * N))[m4];
        float4 vv1 = ((const float4*)(vin + 1 * N))[m4];
        float4 vv2 = ((const float4*)(vin + 2 * N))[m4];
        float4 vv3 = ((const float4*)(vin + 3 * N))[m4];
        #pragma unroll
        for (int i = 0; i < 4; i++) {
            float4 a = ((const float4*)(A + (size_t)i * NN + (size_t)n * N))[m4];
            float d0 = a.x * vv0.x + a.y * vv0.y + a.z * vv0.z + a.w * vv0.w;
            float d1 = a.x * vv1.x + a.y * vv1.y + a.z * vv1.z + a.w * vv1.w;
            float d2 = a.x * vv2.x + a.y * vv2.y + a.z * vv2.z + a.w * vv2.w;
            float d3 = a.x * vv3.x + a.y * vv3.y + a.z * vv3.z + a.w * vv3.w;
            acc0 = fmaf(w[0 * 4 + i], d0, acc0);
            acc1 = fmaf(w[1 * 4 + i], d1, acc1);
            acc2 = fmaf(w[2 * 4 + i], d2, acc2);
            acc3 = fmaf(w[3 * 4 + i], d3, acc3);
        }
    }
    #pragma unroll
    for (int off = 16; off > 0; off >>= 1) {
        acc0 += __shfl_down_sync(0xffffffffu, acc0, off);
        acc1 += __shfl_down_sync(0xffffffffu, acc1, off);
        acc2 += __shfl_down_sync(0xffffffffu, acc2, off);
        acc3 += __shfl_down_sync(0xffffffffu, acc3, off);
    }
    __shared__ float red[8][4];
    int lane = tid & 31, wid = tid >> 5;
    if (lane == 0) { red[wid][0] = acc0; red[wid][1] = acc1; red[wid][2] = acc2; red[wid][3] = acc3; }
    __syncthreads();
    if (tid < 4) {
        float s = 0.f;
        #pragma unroll
        for (int wv = 0; wv < 8; wv++) s += red[wv][tid];
        vout[tid * N + n] = s;
    }
}

// ---------------- d = (v3+1)^-1/2 ; Sp = diag(d) @ support ----------------
// grid: N blocks, 128 threads
__global__ void k_dSp() {
    int n = blockIdx.x, f = threadIdx.x;
    float s = g_support[(size_t)n * F + f];
    #pragma unroll
    for (int c = 0; c < 4; c++) {
        float deg = g_v3[c * N + n] + 1.0f;
        float d = (deg > 0.f) ? rsqrtf(deg) : 0.f;
        g_Sp[((size_t)(c * N + n)) * F + f] = d * s;
        if (f == c) g_d[c * N + n] = d;
    }
}

// ---------------- main GEMM stage ----------------
// Y_c = sum_i w[c,i] * A_i @ X_c  (mixture fused into A tile load)
// stage 0: w=fw3, X=g_Sp -> g_T0
// stage 1: w=fw2, X=g_T0 -> g_T1
// stage 2: w=fw1, X=g_T1 -> fused epilogue: out[n, c*F+f] = relu(d*(acc+Sp)+b)
// grid: (N/64, 4), 256 threads. BM=64, BK=16, per-thread 4x8 register tile.
__device__ __forceinline__ float4 mix4(float4 a0, float4 a1, float4 a2, float4 a3,
                                       float w0, float w1, float w2, float w3) {
    float4 r;
    r.x = w0 * a0.x + w1 * a1.x + w2 * a2.x + w3 * a3.x;
    r.y = w0 * a0.y + w1 * a1.y + w2 * a2.y + w3 * a3.y;
    r.z = w0 * a0.z + w1 * a1.z + w2 * a2.z + w3 * a3.z;
    r.w = w0 * a0.w + w1 * a1.w + w2 * a2.w + w3 * a3.w;
    return r;
}

__global__ void __launch_bounds__(256) k_gemm(const float* __restrict__ A,
                                              const float* __restrict__ bias,
                                              float* __restrict__ out,
                                              int stage) {
    const float* wsrc = (stage == 0) ? g_fw[2] : (stage == 1) ? g_fw[1] : g_fw[0];
    const float* __restrict__ Xin = (stage == 0) ? g_Sp : (stage == 1) ? g_T0 : g_T1;
    float* __restrict__ Yout = (stage == 0) ? g_T0 : g_T1;

    __shared__ float As[2][16][64];    // [k][m], mixed  (8 KB)
    __shared__ float Xs[2][16][128];   // [k][f]         (16 KB)

    const int c = blockIdx.y;
    const int n0 = blockIdx.x * 64;
    const int tid = threadIdx.x;
    const float w0 = wsrc[c * 4 + 0], w1 = wsrc[c * 4 + 1];
    const float w2 = wsrc[c * 4 + 2], w3 = wsrc[c * 4 + 3];
    const size_t NN = (size_t)N * N;
    const float* __restrict__ Xc = Xin + (size_t)c * N * F;

    // output register tile mapping
    const int ry = tid & 15, cx = tid >> 4;
    const int r0 = ry * 4, f0 = cx * 8;

    // A load mapping: one float4 (along k) per thread
    const int kk4 = (tid & 3) * 4;       // 0,4,8,12
    const int mm = tid >> 2;             // 0..63
    const float* aptr = A + (size_t)(n0 + mm) * N + kk4;

    // X load mapping: two float4 per thread
    const int kkx = tid >> 5;            // 0..7
    const int ffx = (tid & 31) * 4;      // 0..124

    float acc[4][8];
    #pragma unroll
    for (int i = 0; i < 4; i++)
        #pragma unroll
        for (int j = 0; j < 8; j++) acc[i][j] = 0.f;

    float4 amix, xv0, xv1;
    // fetch kb = 0
    {
        const float* ap = aptr;
        float4 a0 = *(const float4*)(ap);
        float4 a1 = *(const float4*)(ap + NN);
        float4 a2 = *(const float4*)(ap + 2 * NN);
        float4 a3 = *(const float4*)(ap + 3 * NN);
        amix = mix4(a0, a1, a2, a3, w0, w1, w2, w3);
        xv0 = *(const float4*)(Xc + (size_t)(kkx) * F + ffx);
        xv1 = *(const float4*)(Xc + (size_t)(kkx + 8) * F + ffx);
    }
    // stash buffer 0
    As[0][kk4 + 0][mm] = amix.x;
    As[0][kk4 + 1][mm] = amix.y;
    As[0][kk4 + 2][mm] = amix.z;
    As[0][kk4 + 3][mm] = amix.w;
    *(float4*)&Xs[0][kkx][ffx] = xv0;
    *(float4*)&Xs[0][kkx + 8][ffx] = xv1;
    __syncthreads();

    const int NKB = N / 16;   // 128
    for (int kb = 0; kb < NKB; kb++) {
        const int cur = kb & 1;
        const int nxt = cur ^ 1;
        if (kb + 1 < NKB) {
            const float* ap = aptr + (kb + 1) * 16;
            float4 a0 = *(const float4*)(ap);
            float4 a1 = *(const float4*)(ap + NN);
            float4 a2 = *(const float4*)(ap + 2 * NN);
            float4 a3 = *(const float4*)(ap + 3 * NN);
            amix = mix4(a0, a1, a2, a3, w0, w1, w2, w3);
            xv0 = *(const float4*)(Xc + (size_t)((kb + 1) * 16 + kkx) * F + ffx);
            xv1 = *(const float4*)(Xc + (size_t)((kb + 1) * 16 + kkx + 8) * F + ffx);
        }
        #pragma unroll
        for (int kk = 0; kk < 16; kk++) {
            float4 av = *(const float4*)(&As[cur][kk][r0]);
            float4 x0 = *(const float4*)(&Xs[cur][kk][f0]);
            float4 x1 = *(const float4*)(&Xs[cur][kk][f0 + 4]);
            float ar[4] = {av.x, av.y, av.z, av.w};
            float xr[8] = {x0.x, x0.y, x0.z, x0.w, x1.x, x1.y, x1.z, x1.w};
            #pragma unroll
            for (int i = 0; i < 4; i++)
                #pragma unroll
                for (int j = 0; j < 8; j++)
                    acc[i][j] = fmaf(ar[i], xr[j], acc[i][j]);
        }
        if (kb + 1 < NKB) {
            As[nxt][kk4 + 0][mm] = amix.x;
            As[nxt][kk4 + 1][mm] = amix.y;
            As[nxt][kk4 + 2][mm] = amix.z;
            As[nxt][kk4 + 3][mm] = amix.w;
            *(float4*)&Xs[nxt][kkx][ffx] = xv0;
            *(float4*)&Xs[nxt][kkx + 8][ffx] = xv1;
        }
        __syncthreads();
    }

    if (stage < 2) {
        float* Yc = Yout + (size_t)c * N * F;
        #pragma unroll
        for (int i = 0; i < 4; i++) {
            int n = n0 + r0 + i;
            float4 o0 = make_float4(acc[i][0], acc[i][1], acc[i][2], acc[i][3]);
            float4 o1 = make_float4(acc[i][4], acc[i][5], acc[i][6], acc[i][7]);
            *(float4*)(Yc + (size_t)n * F + f0) = o0;
            *(float4*)(Yc + (size_t)n * F + f0 + 4) = o1;
        }
    } else {
        #pragma unroll
        for (int i = 0; i < 4; i++) {
            int n = n0 + r0 + i;
            float d = g_d[c * N + n];
            const float* sp = g_Sp + ((size_t)(c * N + n)) * F;
            float* op = out + (size_t)n * (C * F) + c * F;
            #pragma unroll
            for (int j = 0; j < 8; j++) {
                float v = d * (acc[i][j] + sp[f0 + j]) + bias[f0 + j];
                op[f0 + j] = fmaxf(v, 0.f);
            }
        }
    }
}

// ---------------- launcher ----------------
extern "C" void kernel_launch(void* const* d_in, const int* in_sizes, int n_in,
                              void* d_out, int out_size) {
    const float* A  = (const float*)d_in[0];   // [E,N,N]
    const float* X  = (const float*)d_in[1];   // [N,WIN]
    const float* w1 = (const float*)d_in[2];   // [C,E]
    const float* w2 = (const float*)d_in[3];   // [C,E]
    const float* w3 = (const float*)d_in[4];   // [C,C]
    const float* gw = (const float*)d_in[5];   // [WIN,F]
    const float* gb = (const float*)d_in[6];   // [F]
    float* out = (float*)d_out;                // [N, C*F]

    k_softmax<<<1, 32>>>(w1, w2, w3);
    k_support<<<N / 32, 256>>>(X, gw);
    k_rowsum<<<E * N, 256>>>(A);
    k_mix_v1<<<N / 256, 256>>>();
    k_matvec<<<N, 256>>>(A, 0);   // v2 = Hb @ v1   (fw2)
    k_matvec<<<N, 256>>>(A, 1);   // v3 = Ha @ v2   (fw1)
    k_dSp<<<N, 128>>>();
    k_gemm<<<dim3(N / 64, C), 256>>>(A, gb, out, 0);   // T0 = Hc @ Sp
    k_gemm<<<dim3(N / 64, C), 256>>>(A, gb, out, 1);   // T1 = Hb @ T0
    k_gemm<<<dim3(N / 64, C), 256>>>(A, gb, out, 2);   // out = relu(d*(Ha@T1 + Sp) + b)
}

// round 2
// speedup vs baseline: 1.0840x; 1.0840x over previous
#include <cuda_runtime.h>
#include <mma.h>
using namespace nvcuda;

#define N 2048
#define E 4
#define C 4
#define F 128      // W_OUT
#define WIN 256

// ---------------- scratch (static device globals; no allocation) ----------------
__device__ float g_fw[3][16];          // softmaxed weights: [0]=fw1, [1]=fw2, [2]=fw3
__device__ float g_support[N * F];     // X @ gcn_w
__device__ float g_v1[C * N];          // Hc @ 1
__device__ float g_v2[C * N];          // Hb @ v1
__device__ float g_v3[C * N];          // Ha @ v2
__device__ float g_d[C * N];           // deg^-1/2
__device__ float g_Sp[C * N * F];      // diag(d) @ support
__device__ float g_T0[C * N * F];
__device__ float g_T1[C * N * F];

// ---------------- tiny: softmax of 4x4 weight rows ----------------
__global__ void k_softmax(const float* __restrict__ w1,
                          const float* __restrict__ w2,
                          const float* __restrict__ w3) {
    int t = threadIdx.x;
    if (t >= 12) return;
    int mat = t >> 2, row = t & 3;
    const float* src = (mat == 0) ? w1 : (mat == 1) ? w2 : w3;
    float a0 = src[row * 4 + 0], a1 = src[row * 4 + 1];
    float a2 = src[row * 4 + 2], a3 = src[row * 4 + 3];
    float mx = fmaxf(fmaxf(a0, a1), fmaxf(a2, a3));
    float e0 = expf(a0 - mx), e1 = expf(a1 - mx), e2 = expf(a2 - mx), e3 = expf(a3 - mx);
    float inv = 1.0f / (e0 + e1 + e2 + e3);
    g_fw[mat][row * 4 + 0] = e0 * inv;
    g_fw[mat][row * 4 + 1] = e1 * inv;
    g_fw[mat][row * 4 + 2] = e2 * inv;
    g_fw[mat][row * 4 + 3] = e3 * inv;
}

// ---------------- support = X @ gcn_w ----------------
__global__ void __launch_bounds__(256) k_support(const float* __restrict__ X,
                                                 const float* __restrict__ W) {
    __shared__ float Xs[32][WIN];   // 32 KB
    int tid = threadIdx.x;
    int row0 = blockIdx.x * 32;
    const float4* Xg = (const float4*)(X + (size_t)row0 * WIN);
    float4* Xs4 = (float4*)&Xs[0][0];
    #pragma unroll
    for (int j = 0; j < (32 * WIN / 4) / 256; j++)
        Xs4[tid + j * 256] = Xg[tid + j * 256];
    __syncthreads();
    int f = tid & 127, ty = tid >> 7;
    float acc[16];
    #pragma unroll
    for (int r = 0; r < 16; r++) acc[r] = 0.f;
    for (int k = 0; k < WIN; k++) {
        float w = W[k * F + f];
        #pragma unroll
        for (int r = 0; r < 16; r++)
            acc[r] = fmaf(Xs[ty * 16 + r][k], w, acc[r]);
    }
    #pragma unroll
    for (int r = 0; r < 16; r++)
        g_support[(size_t)(row0 + ty * 16 + r) * F + f] = acc[r];
}

// ---------------- fused rowsums of A_i + fw3-mix -> v1 ----------------
// grid: N blocks, 256 threads; block n reads row n of all 4 edge types
__global__ void __launch_bounds__(256) k_rowsum_mix(const float* __restrict__ A) {
    int n = blockIdx.x;
    int tid = threadIdx.x;
    const size_t NN = (size_t)N * N;
    float s[4] = {0.f, 0.f, 0.f, 0.f};
    #pragma unroll
    for (int it = 0; it < (N / 4) / 256; it++) {
        int m4 = tid + it * 256;
        #pragma unroll
        for (int e = 0; e < 4; e++) {
            float4 v = ((const float4*)(A + (size_t)e * NN + (size_t)n * N))[m4];
            s[e] += v.x + v.y + v.z + v.w;
        }
    }
    #pragma unroll
    for (int off = 16; off > 0; off >>= 1)
        #pragma unroll
        for (int e = 0; e < 4; e++)
            s[e] += __shfl_down_sync(0xffffffffu, s[e], off);
    __shared__ float red[8][4];
    int lane = tid & 31, wid = tid >> 5;
    if (lane == 0) { red[wid][0] = s[0]; red[wid][1] = s[1]; red[wid][2] = s[2]; red[wid][3] = s[3]; }
    __syncthreads();
    if (tid < 4) {
        // tid = channel c ; first reduce all 4 edge sums, then mix with fw3
        float r[4];
        #pragma unroll
        for (int e = 0; e < 4; e++) {
            float t = 0.f;
            #pragma unroll
            for (int w = 0; w < 8; w++) t += red[w][e];
            r[e] = t;
        }
        g_v1[tid * N + n] = g_fw[2][tid * 4 + 0] * r[0] + g_fw[2][tid * 4 + 1] * r[1]
                          + g_fw[2][tid * 4 + 2] * r[2] + g_fw[2][tid * 4 + 3] * r[3];
    }
}

// ---------------- vout_c = sum_i w[c,i] * (A_i @ vin_c) ----------------
__global__ void __launch_bounds__(256) k_matvec(const float* __restrict__ A, int stage) {
    const float* __restrict__ vin = (stage == 0) ? g_v1 : g_v2;
    float* __restrict__ vout = (stage == 0) ? g_v2 : g_v3;
    const float* wsrc = (stage == 0) ? g_fw[1] : g_fw[0];
    int n = blockIdx.x;
    int tid = threadIdx.x;
    float w[16];
    #pragma unroll
    for (int j = 0; j < 16; j++) w[j] = wsrc[j];
    float acc0 = 0.f, acc1 = 0.f, acc2 = 0.f, acc3 = 0.f;
    const size_t NN = (size_t)N * N;
    #pragma unroll
    for (int it = 0; it < (N / 4) / 256; it++) {
        int m4 = tid + it * 256;
        float4 vv0 = ((const float4*)(vin + 0 * N))[m4];
        float4 vv1 = ((const float4*)(vin + 1 * N))[m4];
        float4 vv2 = ((const float4*)(vin + 2 * N))[m4];
        float4 vv3 = ((const float4*)(vin + 3 * N))[m4];
        #pragma unroll
        for (int i = 0; i < 4; i++) {
            float4 a = ((const float4*)(A + (size_t)i * NN + (size_t)n * N))[m4];
            float d0 = a.x * vv0.x + a.y * vv0.y + a.z * vv0.z + a.w * vv0.w;
            float d1 = a.x * vv1.x + a.y * vv1.y + a.z * vv1.z + a.w * vv1.w;
            float d2 = a.x * vv2.x + a.y * vv2.y + a.z * vv2.z + a.w * vv2.w;
            float d3 = a.x * vv3.x + a.y * vv3.y + a.z * vv3.z + a.w * vv3.w;
            acc0 = fmaf(w[0 * 4 + i], d0, acc0);
            acc1 = fmaf(w[1 * 4 + i], d1, acc1);
            acc2 = fmaf(w[2 * 4 + i], d2, acc2);
            acc3 = fmaf(w[3 * 4 + i], d3, acc3);
        }
    }
    #pragma unroll
    for (int off = 16; off > 0; off >>= 1) {
        acc0 += __shfl_down_sync(0xffffffffu, acc0, off);
        acc1 += __shfl_down_sync(0xffffffffu, acc1, off);
        acc2 += __shfl_down_sync(0xffffffffu, acc2, off);
        acc3 += __shfl_down_sync(0xffffffffu, acc3, off);
    }
    __shared__ float red[8][4];
    int lane = tid & 31, wid = tid >> 5;
    if (lane == 0) { red[wid][0] = acc0; red[wid][1] = acc1; red[wid][2] = acc2; red[wid][3] = acc3; }
    __syncthreads();
    if (tid < 4) {
        float s = 0.f;
        #pragma unroll
        for (int wv = 0; wv < 8; wv++) s += red[wv][tid];
        vout[tid * N + n] = s;
    }
}

// ---------------- d = (v3+1)^-1/2 ; Sp = diag(d) @ support ----------------
__global__ void k_dSp() {
    int n = blockIdx.x, f = threadIdx.x;
    float s = g_support[(size_t)n * F + f];
    #pragma unroll
    for (int c = 0; c < 4; c++) {
        float deg = g_v3[c * N + n] + 1.0f;
        float d = (deg > 0.f) ? rsqrtf(deg) : 0.f;
        g_Sp[((size_t)(c * N + n)) * F + f] = d * s;
        if (f == c) g_d[c * N + n] = d;
    }
}

// ---------------- main GEMM stage: tf32 tensor cores ----------------
// Y_c = sum_i w[c,i] * A_i @ X_c  (mixture fused into A tile load, fp32 mix -> tf32)
// BM=64, BN=F=128, BK=16, 256 threads (8 warps), warp tile 16x64.
// grid (32, 4). Double-buffered smem, register-staged global loads.
#define BM 64
#define BK 16
#define LDA 20            // BK + 4 pad
#define LDX 132           // F + 4 pad
#define AS_SZ (BM * LDA)  // 1280
#define XS_SZ (BK * LDX)  // 2112

__device__ __forceinline__ float4 mix4(float4 a0, float4 a1, float4 a2, float4 a3,
                                       float w0, float w1, float w2, float w3) {
    float4 r;
    r.x = w0 * a0.x + w1 * a1.x + w2 * a2.x + w3 * a3.x;
    r.y = w0 * a0.y + w1 * a1.y + w2 * a2.y + w3 * a3.y;
    r.z = w0 * a0.z + w1 * a1.z + w2 * a2.z + w3 * a3.z;
    r.w = w0 * a0.w + w1 * a1.w + w2 * a2.w + w3 * a3.w;
    return r;
}

__global__ void __launch_bounds__(256) k_gemm_tc(const float* __restrict__ A,
                                                 const float* __restrict__ bias,
                                                 float* __restrict__ out,
                                                 int stage) {
    __shared__ float sm[8192];   // 32 KB: As[2] (2x1280) + Xs[2] (2x2112) = 6784 used;
                                 // full 8192 reused as 64x128 C-stage buffer in epilogue
    float* As[2] = { sm, sm + AS_SZ };
    float* Xs[2] = { sm + 2 * AS_SZ, sm + 2 * AS_SZ + XS_SZ };

    const float* wsrc = (stage == 0) ? g_fw[2] : (stage == 1) ? g_fw[1] : g_fw[0];
    const float* __restrict__ Xin = (stage == 0) ? g_Sp : (stage == 1) ? g_T0 : g_T1;
    float* __restrict__ Yout = (stage == 0) ? g_T0 : g_T1;

    const int c = blockIdx.y;
    const int n0 = blockIdx.x * BM;
    const int tid = threadIdx.x;
    const int warp = tid >> 5;
    const int wm = warp >> 1;          // 0..3 -> M offset wm*16
    const int wn = warp & 1;           // 0..1 -> N offset wn*64
    const float w0 = wsrc[c * 4 + 0], w1 = wsrc[c * 4 + 1];
    const float w2 = wsrc[c * 4 + 2], w3 = wsrc[c * 4 + 3];
    const size_t NN = (size_t)N * N;
    const float* __restrict__ Xc = Xin + (size_t)c * N * F;

    // A global-load mapping: one float4 per edge type per thread
    const int am = tid >> 2;           // 0..63
    const int ak = (tid & 3) * 4;      // 0,4,8,12
    const float* aptr = A + (size_t)(n0 + am) * N + ak;
    // X global-load mapping: two float4 per thread
    const int xk = tid >> 4;           // 0..15
    const int xf = (tid & 15) * 8;     // 0..120

    wmma::fragment<wmma::accumulator, 16, 16, 8, float> cf[4];
    #pragma unroll
    for (int j = 0; j < 4; j++) wmma::fill_fragment(cf[j], 0.0f);

    float4 ra0, ra1, ra2, ra3, rx0, rx1;
    // fetch kb=0
    ra0 = *(const float4*)(aptr);
    ra1 = *(const float4*)(aptr + NN);
    ra2 = *(const float4*)(aptr + 2 * NN);
    ra3 = *(const float4*)(aptr + 3 * NN);
    rx0 = *(const float4*)(Xc + (size_t)xk * F + xf);
    rx1 = *(const float4*)(Xc + (size_t)xk * F + xf + 4);
    {
        float4 amix = mix4(ra0, ra1, ra2, ra3, w0, w1, w2, w3);
        *(float4*)&As[0][am * LDA + ak] = amix;
        *(float4*)&Xs[0][xk * LDX + xf] = rx0;
        *(float4*)&Xs[0][xk * LDX + xf + 4] = rx1;
    }
    __syncthreads();

    const int NKB = N / BK;   // 128
    for (int kb = 0; kb < NKB; kb++) {
        const int cur = kb & 1;
        const int nxt = cur ^ 1;
        if (kb + 1 < NKB) {
            const float* ap = aptr + (kb + 1) * BK;
            ra0 = *(const float4*)(ap);
            ra1 = *(const float4*)(ap + NN);
            ra2 = *(const float4*)(ap + 2 * NN);
            ra3 = *(const float4*)(ap + 3 * NN);
            rx0 = *(const float4*)(Xc + (size_t)((kb + 1) * BK + xk) * F + xf);
            rx1 = *(const float4*)(Xc + (size_t)((kb + 1) * BK + xk) * F + xf + 4);
        }
        #pragma unroll
        for (int ks = 0; ks < 2; ks++) {
            wmma::fragment<wmma::matrix_a, 16, 16, 8, wmma::precision::tf32, wmma::row_major> af;
            wmma::load_matrix_sync(af, &As[cur][(wm * 16) * LDA + ks * 8], LDA);
            #pragma unroll
            for (int i = 0; i < af.num_elements; i++) af.x[i] = wmma::__float_to_tf32(af.x[i]);
            #pragma unroll
            for (int j = 0; j < 4; j++) {
                wmma::fragment<wmma::matrix_b, 16, 16, 8, wmma::precision::tf32, wmma::row_major> bf;
                wmma::load_matrix_sync(bf, &Xs[cur][(ks * 8) * LDX + wn * 64 + j * 16], LDX);
                #pragma unroll
                for (int i = 0; i < bf.num_elements; i++) bf.x[i] = wmma::__float_to_tf32(bf.x[i]);
                wmma::mma_sync(cf[j], af, bf, cf[j]);
            }
        }
        if (kb + 1 < NKB) {
            float4 amix = mix4(ra0, ra1, ra2, ra3, w0, w1, w2, w3);
            *(float4*)&As[nxt][am * LDA + ak] = amix;
            *(float4*)&Xs[nxt][xk * LDX + xf] = rx0;
            *(float4*)&Xs[nxt][xk * LDX + xf + 4] = rx1;
        }
        __syncthreads();
    }

    if (stage < 2) {
        float* Yc = Yout + (size_t)c * N * F;
        #pragma unroll
        for (int j = 0; j < 4; j++)
            wmma::store_matrix_sync(Yc + (size_t)(n0 + wm * 16) * F + wn * 64 + j * 16,
                                    cf[j], F, wmma::mem_row_major);
    } else {
        // park accumulators in smem (reuse), then fused epilogue
        __syncthreads();
        #pragma unroll
        for (int j = 0; j < 4; j++)
            wmma::store_matrix_sync(&sm[(wm * 16) * F + wn * 64 + j * 16],
                                    cf[j], F, wmma::mem_row_major);
        __syncthreads();
        const int r = tid >> 2;           // 0..63
        const int fc = (tid & 3) * 32;    // 0,32,64,96
        const int n = n0 + r;
        const float d = g_d[c * N + n];
        const float* sp = g_Sp + ((size_t)(c * N + n)) * F;
        float* op = out + (size_t)n * (C * F) + c * F;
        #pragma unroll
        for (int j0 = 0; j0 < 32; j0 += 4) {
            float4 a4 = *(const float4*)&sm[r * F + fc + j0];
            float4 s4 = *(const float4*)(sp + fc + j0);
            float4 b4 = *(const float4*)(bias + fc + j0);
            float4 o;
            o.x = fmaxf(d * (a4.x + s4.x) + b4.x, 0.f);
            o.y = fmaxf(d * (a4.y + s4.y) + b4.y, 0.f);
            o.z = fmaxf(d * (a4.z + s4.z) + b4.z, 0.f);
            o.w = fmaxf(d * (a4.w + s4.w) + b4.w, 0.f);
            *(float4*)(op + fc + j0) = o;
        }
    }
}

// ---------------- launcher ----------------
extern "C" void kernel_launch(void* const* d_in, const int* in_sizes, int n_in,
                              void* d_out, int out_size) {
    const float* A  = (const float*)d_in[0];   // [E,N,N]
    const float* X  = (const float*)d_in[1];   // [N,WIN]
    const float* w1 = (const float*)d_in[2];   // [C,E]
    const float* w2 = (const float*)d_in[3];   // [C,E]
    const float* w3 = (const float*)d_in[4];   // [C,C]
    const float* gw = (const float*)d_in[5];   // [WIN,F]
    const float* gb = (const float*)d_in[6];   // [F]
    float* out = (float*)d_out;                // [N, C*F]

    k_softmax<<<1, 32>>>(w1, w2, w3);
    k_support<<<N / 32, 256>>>(X, gw);
    k_rowsum_mix<<<N, 256>>>(A);              // v1 = Hc @ 1   (fw3)
    k_matvec<<<N, 256>>>(A, 0);               // v2 = Hb @ v1  (fw2)
    k_matvec<<<N, 256>>>(A, 1);               // v3 = Ha @ v2  (fw1)
    k_dSp<<<N, 128>>>();
    k_gemm_tc<<<dim3(N / BM, C), 256>>>(A, gb, out, 0);   // T0 = Hc @ Sp
    k_gemm_tc<<<dim3(N / BM, C), 256>>>(A, gb, out, 1);   // T1 = Hb @ T0
    k_gemm_tc<<<dim3(N / BM, C), 256>>>(A, gb, out, 2);   // out = relu(d*(Ha@T1+Sp)+b)
}

// round 3
// speedup vs baseline: 1.4912x; 1.3757x over previous
#include <cuda_runtime.h>
#include <mma.h>
#include <cstdint>
using namespace nvcuda;

#define N 2048
#define E 4
#define C 4
#define F 128      // W_OUT
#define WIN 256

// ---------------- scratch (static device globals; no allocation) ----------------
__device__ float g_fw[3][16];            // softmaxed weights: [0]=fw1, [1]=fw2, [2]=fw3
__device__ float g_support[N * F];       // X @ gcn_w
__device__ float g_v1[C * N];            // rowsums of stage0 mix (Hc @ 1)
__device__ float g_v2[C * N];            // Hb @ v1
__device__ float g_v3[C * N];            // Ha @ v2
__device__ float g_d[C * N];             // deg^-1/2
__device__ float g_Sp[C * N * F];        // diag(d) @ support
__device__ float g_T0[C * N * F];
__device__ float g_T1[C * N * F];
// premixed adjacency: [stage][channel][N][N]; stage s uses weights g_fw[2-s]
__device__ float g_Am[3 * C * (size_t)N * N];   // 201 MB

// ---------------- tiny: softmax of 4x4 weight rows ----------------
__global__ void k_softmax(const float* __restrict__ w1,
                          const float* __restrict__ w2,
                          const float* __restrict__ w3) {
    int t = threadIdx.x;
    if (t >= 12) return;
    int mat = t >> 2, row = t & 3;
    const float* src = (mat == 0) ? w1 : (mat == 1) ? w2 : w3;
    float a0 = src[row * 4 + 0], a1 = src[row * 4 + 1];
    float a2 = src[row * 4 + 2], a3 = src[row * 4 + 3];
    float mx = fmaxf(fmaxf(a0, a1), fmaxf(a2, a3));
    float e0 = expf(a0 - mx), e1 = expf(a1 - mx), e2 = expf(a2 - mx), e3 = expf(a3 - mx);
    float inv = 1.0f / (e0 + e1 + e2 + e3);
    g_fw[mat][row * 4 + 0] = e0 * inv;
    g_fw[mat][row * 4 + 1] = e1 * inv;
    g_fw[mat][row * 4 + 2] = e2 * inv;
    g_fw[mat][row * 4 + 3] = e3 * inv;
}

// ---------------- support = X @ gcn_w ----------------
__global__ void __launch_bounds__(256) k_support(const float* __restrict__ X,
                                                 const float* __restrict__ W) {
    __shared__ float Xs[32][WIN];   // 32 KB
    int tid = threadIdx.x;
    int row0 = blockIdx.x * 32;
    const float4* Xg = (const float4*)(X + (size_t)row0 * WIN);
    float4* Xs4 = (float4*)&Xs[0][0];
    #pragma unroll
    for (int j = 0; j < (32 * WIN / 4) / 256; j++)
        Xs4[tid + j * 256] = Xg[tid + j * 256];
    __syncthreads();
    int f = tid & 127, ty = tid >> 7;
    float acc[16];
    #pragma unroll
    for (int r = 0; r < 16; r++) acc[r] = 0.f;
    for (int k = 0; k < WIN; k++) {
        float w = W[k * F + f];
        #pragma unroll
        for (int r = 0; r < 16; r++)
            acc[r] = fmaf(Xs[ty * 16 + r][k], w, acc[r]);
    }
    #pragma unroll
    for (int r = 0; r < 16; r++)
        g_support[(size_t)(row0 + ty * 16 + r) * F + f] = acc[r];
}

// ---------------- premix: A -> 12 mixed planes + stage0 rowsums (v1) ----------------
// grid: N blocks (one n-row each), 256 threads
__global__ void __launch_bounds__(256) k_premix(const float* __restrict__ A) {
    const int n = blockIdx.x;
    const int tid = threadIdx.x;
    const size_t NN = (size_t)N * N;
    // local copy of all weights
    __shared__ float w[3][16];
    if (tid < 48) ((float*)w)[tid] = ((const float*)g_fw)[tid];
    __syncthreads();

    float acc[4] = {0.f, 0.f, 0.f, 0.f};   // stage0 channel rowsums
    #pragma unroll
    for (int it = 0; it < (N / 4) / 256; it++) {
        int m4 = tid + it * 256;
        float4 e0 = ((const float4*)(A + 0 * NN + (size_t)n * N))[m4];
        float4 e1 = ((const float4*)(A + 1 * NN + (size_t)n * N))[m4];
        float4 e2 = ((const float4*)(A + 2 * NN + (size_t)n * N))[m4];
        float4 e3 = ((const float4*)(A + 3 * NN + (size_t)n * N))[m4];
        #pragma unroll
        for (int s = 0; s < 3; s++) {
            const float* ws = w[2 - s];
            #pragma unroll
            for (int c = 0; c < 4; c++) {
                float w0 = ws[c * 4 + 0], w1 = ws[c * 4 + 1];
                float w2 = ws[c * 4 + 2], w3 = ws[c * 4 + 3];
                float4 o;
                o.x = w0 * e0.x + w1 * e1.x + w2 * e2.x + w3 * e3.x;
                o.y = w0 * e0.y + w1 * e1.y + w2 * e2.y + w3 * e3.y;
                o.z = w0 * e0.z + w1 * e1.z + w2 * e2.z + w3 * e3.z;
                o.w = w0 * e0.w + w1 * e1.w + w2 * e2.w + w3 * e3.w;
                ((float4*)(g_Am + (size_t)(s * 4 + c) * NN + (size_t)n * N))[m4] = o;
                if (s == 0) acc[c] += o.x + o.y + o.z + o.w;
            }
        }
    }
    // reduce stage0 rowsums -> g_v1
    #pragma unroll
    for (int off = 16; off > 0; off >>= 1)
        #pragma unroll
        for (int c = 0; c < 4; c++)
            acc[c] += __shfl_down_sync(0xffffffffu, acc[c], off);
    __shared__ float red[8][4];
    int lane = tid & 31, wid = tid >> 5;
    if (lane == 0) { red[wid][0] = acc[0]; red[wid][1] = acc[1]; red[wid][2] = acc[2]; red[wid][3] = acc[3]; }
    __syncthreads();
    if (tid < 4) {
        float s = 0.f;
        #pragma unroll
        for (int wv = 0; wv < 8; wv++) s += red[wv][tid];
        g_v1[tid * N + n] = s;
    }
}

// ---------------- matvec on premixed planes ----------------
// stage 0: v2_c = Am[1][c] @ v1_c ; stage 1: v3_c = Am[2][c] @ v2_c
__global__ void __launch_bounds__(256) k_matvec_p(int stage) {
    const float* __restrict__ vin = (stage == 0) ? g_v1 : g_v2;
    float* __restrict__ vout = (stage == 0) ? g_v2 : g_v3;
    const float* __restrict__ Am = g_Am + (size_t)(stage + 1) * 4 * (size_t)N * N;
    const int n = blockIdx.x;
    const int tid = threadIdx.x;
    const size_t NN = (size_t)N * N;
    float acc[4] = {0.f, 0.f, 0.f, 0.f};
    #pragma unroll
    for (int it = 0; it < (N / 4) / 256; it++) {
        int m4 = tid + it * 256;
        #pragma unroll
        for (int c = 0; c < 4; c++) {
            float4 a = ((const float4*)(Am + (size_t)c * NN + (size_t)n * N))[m4];
            float4 v = ((const float4*)(vin + c * N))[m4];
            acc[c] += a.x * v.x + a.y * v.y + a.z * v.z + a.w * v.w;
        }
    }
    #pragma unroll
    for (int off = 16; off > 0; off >>= 1)
        #pragma unroll
        for (int c = 0; c < 4; c++)
            acc[c] += __shfl_down_sync(0xffffffffu, acc[c], off);
    __shared__ float red[8][4];
    int lane = tid & 31, wid = tid >> 5;
    if (lane == 0) { red[wid][0] = acc[0]; red[wid][1] = acc[1]; red[wid][2] = acc[2]; red[wid][3] = acc[3]; }
    __syncthreads();
    if (tid < 4) {
        float s = 0.f;
        #pragma unroll
        for (int wv = 0; wv < 8; wv++) s += red[wv][tid];
        vout[tid * N + n] = s;
    }
}

// ---------------- d = (v3+1)^-1/2 ; Sp = diag(d) @ support ----------------
__global__ void k_dSp() {
    int n = blockIdx.x, f = threadIdx.x;
    float s = g_support[(size_t)n * F + f];
    #pragma unroll
    for (int c = 0; c < 4; c++) {
        float deg = g_v3[c * N + n] + 1.0f;
        float d = (deg > 0.f) ? rsqrtf(deg) : 0.f;
        g_Sp[((size_t)(c * N + n)) * F + f] = d * s;
        if (f == c) g_d[c * N + n] = d;
    }
}

// ---------------- main GEMM: tf32 wmma + cp.async 4-stage on premixed A ----------------
// Y_c = Am[s][c] @ X_c.  BM=64, BN=F=128, BK=32, 256 threads, warp tile 32x32.
// grid (32, 4). A via cp.async 4-deep, X via reg double-buffer.
#define BKg 32
#define LDAg 36            // 32 + 4 pad (floats)
#define LDXg 132           // 128 + 4 pad
#define AS_FLOATS (64 * LDAg)      // 2304 per stage buf
#define XS_FLOATS (BKg * LDXg)     // 4224 per buf
#define GEMM_SMEM_BYTES ((4 * AS_FLOATS + 2 * XS_FLOATS) * 4)   // 70656

__device__ __forceinline__ void cp_async16(uint32_t smem_addr, const void* gptr) {
    asm volatile("cp.async.ca.shared.global [%0], [%1], 16;" :: "r"(smem_addr), "l"(gptr));
}
__device__ __forceinline__ void cp_commit() { asm volatile("cp.async.commit_group;"); }
__device__ __forceinline__ void cp_wait2() { asm volatile("cp.async.wait_group 2;"); }

__global__ void __launch_bounds__(256) k_gemm_p(const float* __restrict__ bias,
                                                float* __restrict__ out,
                                                int stage) {
    extern __shared__ float sm[];
    float* Asb = sm;                          // 4 stage buffers
    float* Xsb = sm + 4 * AS_FLOATS;          // 2 buffers

    const size_t NN = (size_t)N * N;
    const int c = blockIdx.y;
    const int n0 = blockIdx.x * 64;
    const int tid = threadIdx.x;
    const int warp = tid >> 5;
    const int wm = warp >> 2;          // 0..1
    const int wn = warp & 3;           // 0..3
    const float* __restrict__ Ain = g_Am + (size_t)(stage * 4 + c) * NN;
    const float* __restrict__ Xin = ((stage == 0) ? g_Sp : (stage == 1) ? g_T0 : g_T1)
                                    + (size_t)c * N * F;
    float* __restrict__ Yout = ((stage == 0) ? g_T0 : g_T1) + (size_t)c * N * F;

    // cp.async A mapping: 512 x 16B chunks per tile; thread handles 2
    const int arow0 = tid >> 3;               // chunk q=tid
    const int ac0 = (tid & 7) * 4;
    const int arow1 = (tid + 256) >> 3;       // chunk q=tid+256
    const int ac1 = ((tid + 256) & 7) * 4;
    const uint32_t as_base = (uint32_t)__cvta_generic_to_shared(Asb);
    const uint32_t xs_base = (uint32_t)__cvta_generic_to_shared(Xsb);

    // X LDG mapping: 4 float4 per thread
    const int xrow[4] = { (tid) >> 5, (tid + 256) >> 5, (tid + 512) >> 5, (tid + 768) >> 5 };
    const int xcol = (tid & 31) * 4;

    wmma::fragment<wmma::accumulator, 16, 16, 8, float> cf[2][2];
    #pragma unroll
    for (int i = 0; i < 2; i++)
        #pragma unroll
        for (int j = 0; j < 2; j++) wmma::fill_fragment(cf[i][j], 0.0f);

    const int NKB = N / BKg;   // 64

    // prologue: issue A stages kb=0..2
    #pragma unroll
    for (int p = 0; p < 3; p++) {
        uint32_t dst = as_base + (uint32_t)(p * AS_FLOATS) * 4;
        cp_async16(dst + (arow0 * LDAg + ac0) * 4, Ain + (size_t)(n0 + arow0) * N + p * BKg + ac0);
        cp_async16(dst + (arow1 * LDAg + ac1) * 4, Ain + (size_t)(n0 + arow1) * N + p * BKg + ac1);
        cp_commit();
    }
    // prologue: X kb=0 -> Xs[0]
    {
        float4 rx[4];
        #pragma unroll
        for (int j = 0; j < 4; j++)
            rx[j] = *(const float4*)(Xin + (size_t)xrow[j] * F + xcol);
        #pragma unroll
        for (int j = 0; j < 4; j++)
            *(float4*)&Xsb[xrow[j] * LDXg + xcol] = rx[j];
    }

    float4 rx[4];
    for (int kb = 0; kb < NKB; kb++) {
        // prefetch X for kb+1 into regs
        if (kb + 1 < NKB) {
            #pragma unroll
            for (int j = 0; j < 4; j++)
                rx[j] = *(const float4*)(Xin + (size_t)((kb + 1) * BKg + xrow[j]) * F + xcol);
        }
        cp_wait2();            // A stage kb ready
        __syncthreads();       // + prev X stores visible; all warps done with As[(kb-1)%4]
        // issue A for kb+3 (always commit to keep group accounting uniform)
        if (kb + 3 < NKB) {
            uint32_t dst = as_base + (uint32_t)(((kb + 3) & 3) * AS_FLOATS) * 4;
            cp_async16(dst + (arow0 * LDAg + ac0) * 4, Ain + (size_t)(n0 + arow0) * N + (kb + 3) * BKg + ac0);
            cp_async16(dst + (arow1 * LDAg + ac1) * 4, Ain + (size_t)(n0 + arow1) * N + (kb + 3) * BKg + ac1);
        }
        cp_commit();

        const float* As = Asb + (kb & 3) * AS_FLOATS;
        const float* Xs = Xsb + (kb & 1) * XS_FLOATS;
        #pragma unroll
        for (int ks = 0; ks < 4; ks++) {
            wmma::fragment<wmma::matrix_a, 16, 16, 8, wmma::precision::tf32, wmma::row_major> af[2];
            #pragma unroll
            for (int i = 0; i < 2; i++) {
                wmma::load_matrix_sync(af[i], As + (wm * 32 + i * 16) * LDAg + ks * 8, LDAg);
                #pragma unroll
                for (int u = 0; u < af[i].num_elements; u++)
                    af[i].x[u] = wmma::__float_to_tf32(af[i].x[u]);
            }
            #pragma unroll
            for (int j = 0; j < 2; j++) {
                wmma::fragment<wmma::matrix_b, 16, 16, 8, wmma::precision::tf32, wmma::row_major> bf;
                wmma::load_matrix_sync(bf, Xs + (ks * 8) * LDXg + wn * 32 + j * 16, LDXg);
                #pragma unroll
                for (int u = 0; u < bf.num_elements; u++)
                    bf.x[u] = wmma::__float_to_tf32(bf.x[u]);
                #pragma unroll
                for (int i = 0; i < 2; i++)
                    wmma::mma_sync(cf[i][j], af[i], bf, cf[i][j]);
            }
        }
        // store X(kb+1) into other buffer (safe: all warps past barrier => done reading it)
        if (kb + 1 < NKB) {
            float* Xn = Xsb + ((kb + 1) & 1) * XS_FLOATS;
            #pragma unroll
            for (int j = 0; j < 4; j++)
                *(float4*)&Xn[xrow[j] * LDXg + xcol] = rx[j];
        }
    }

    if (stage < 2) {
        #pragma unroll
        for (int i = 0; i < 2; i++)
            #pragma unroll
            for (int j = 0; j < 2; j++)
                wmma::store_matrix_sync(Yout + (size_t)(n0 + wm * 32 + i * 16) * F + wn * 32 + j * 16,
                                        cf[i][j], F, wmma::mem_row_major);
    } else {
        __syncthreads();   // done with smem tiles; reuse as 64x128 C buffer
        #pragma unroll
        for (int i = 0; i < 2; i++)
            #pragma unroll
            for (int j = 0; j < 2; j++)
                wmma::store_matrix_sync(&sm[(wm * 32 + i * 16) * F + wn * 32 + j * 16],
                                        cf[i][j], F, wmma::mem_row_major);
        __syncthreads();
        const int r = tid >> 2;
        const int fc = (tid & 3) * 32;
        const int n = n0 + r;
        const float d = g_d[c * N + n];
        const float* sp = g_Sp + ((size_t)(c * N + n)) * F;
        float* op = out + (size_t)n * (C * F) + c * F;
        #pragma unroll
        for (int j0 = 0; j0 < 32; j0 += 4) {
            float4 a4 = *(const float4*)&sm[r * F + fc + j0];
            float4 s4 = *(const float4*)(sp + fc + j0);
            float4 b4 = *(const float4*)(bias + fc + j0);
            float4 o;
            o.x = fmaxf(d * (a4.x + s4.x) + b4.x, 0.f);
            o.y = fmaxf(d * (a4.y + s4.y) + b4.y, 0.f);
            o.z = fmaxf(d * (a4.z + s4.z) + b4.z, 0.f);
            o.w = fmaxf(d * (a4.w + s4.w) + b4.w, 0.f);
            *(float4*)(op + fc + j0) = o;
        }
    }
}

// ---------------- launcher ----------------
extern "C" void kernel_launch(void* const* d_in, const int* in_sizes, int n_in,
                              void* d_out, int out_size) {
    const float* A  = (const float*)d_in[0];   // [E,N,N]
    const float* X  = (const float*)d_in[1];   // [N,WIN]
    const float* w1 = (const float*)d_in[2];   // [C,E]
    const float* w2 = (const float*)d_in[3];   // [C,E]
    const float* w3 = (const float*)d_in[4];   // [C,C]
    const float* gw = (const float*)d_in[5];   // [WIN,F]
    const float* gb = (const float*)d_in[6];   // [F]
    float* out = (float*)d_out;                // [N, C*F]

    static bool attr_done = false;
    if (!attr_done) {
        cudaFuncSetAttribute(k_gemm_p, cudaFuncAttributeMaxDynamicSharedMemorySize,
                             GEMM_SMEM_BYTES);
        attr_done = true;
    }

    k_softmax<<<1, 32>>>(w1, w2, w3);
    k_support<<<N / 32, 256>>>(X, gw);
    k_premix<<<N, 256>>>(A);                  // 12 mixed planes + v1
    k_matvec_p<<<N, 256>>>(0);                // v2
    k_matvec_p<<<N, 256>>>(1);                // v3
    k_dSp<<<N, 128>>>();
    k_gemm_p<<<dim3(N / 64, C), 256, GEMM_SMEM_BYTES>>>(gb, out, 0);   // T0
    k_gemm_p<<<dim3(N / 64, C), 256, GEMM_SMEM_BYTES>>>(gb, out, 1);   // T1
    k_gemm_p<<<dim3(N / 64, C), 256, GEMM_SMEM_BYTES>>>(gb, out, 2);   // out
}

// round 5
// speedup vs baseline: 1.8313x; 1.2281x over previous
#include <cuda_runtime.h>
#include <cstdint>

#define N 2048
#define E 4
#define C 4
#define F 128      // W_OUT
#define WIN 256
#define NNSZ ((size_t)N * N)
#define NFSZ ((size_t)N * F)

// ---------------- scratch (static device globals; no allocation) ----------------
__device__ float g_fw[3][16];            // softmaxed weights: [0]=fw1, [1]=fw2, [2]=fw3
__device__ float g_support[N * F];       // X @ gcn_w              [n][f]
__device__ float g_v1[C * N];
__device__ float g_v2[C * N];
__device__ float g_v3[C * N];
__device__ float g_d[C * N];             // deg^-1/2
__device__ float g_Sp[C * N * F];        // diag(d)@support natural [c][n][f]
__device__ float g_SpB[C * N * F];       // fragment-order B plane (stage 0)
__device__ float g_T0B[C * N * F];       // fragment-order B plane (stage 1)
__device__ float g_T1B[C * N * F];       // fragment-order B plane (stage 2)
// fragment-ordered premixed adjacency planes: [stage*4 + c], unit = m16 x k8 (128 floats)
// unit index = mt*256 + kt ; float idx within unit = lane*4 + reg, reg mapping = mma A frag
__device__ float g_Am[12 * NNSZ];

__device__ __forceinline__ float to_tf32(float x) {
    float r; asm("cvt.rna.tf32.f32 %0, %1;" : "=f"(r) : "f"(x)); return r;
}

// mma.m16n8k8 tf32: D += A*B, fragments per PTX ISA layout
__device__ __forceinline__ void mma_tf32(float& d0, float& d1, float& d2, float& d3,
                                         uint32_t a0, uint32_t a1, uint32_t a2, uint32_t a3,
                                         uint32_t b0, uint32_t b1) {
    asm volatile(
        "mma.sync.aligned.m16n8k8.row.col.f32.tf32.tf32.f32 "
        "{%0,%1,%2,%3}, {%4,%5,%6,%7}, {%8,%9}, {%0,%1,%2,%3};"
        : "+f"(d0), "+f"(d1), "+f"(d2), "+f"(d3)
        : "r"(a0), "r"(a1), "r"(a2), "r"(a3), "r"(b0), "r"(b1));
}

// ---------------- tiny: softmax of 4x4 weight rows ----------------
__global__ void k_softmax(const float* __restrict__ w1,
                          const float* __restrict__ w2,
                          const float* __restrict__ w3) {
    int t = threadIdx.x;
    if (t >= 12) return;
    int mat = t >> 2, row = t & 3;
    const float* src = (mat == 0) ? w1 : (mat == 1) ? w2 : w3;
    float a0 = src[row * 4 + 0], a1 = src[row * 4 + 1];
    float a2 = src[row * 4 + 2], a3 = src[row * 4 + 3];
    float mx = fmaxf(fmaxf(a0, a1), fmaxf(a2, a3));
    float e0 = expf(a0 - mx), e1 = expf(a1 - mx), e2 = expf(a2 - mx), e3 = expf(a3 - mx);
    float inv = 1.0f / (e0 + e1 + e2 + e3);
    g_fw[mat][row * 4 + 0] = e0 * inv;
    g_fw[mat][row * 4 + 1] = e1 * inv;
    g_fw[mat][row * 4 + 2] = e2 * inv;
    g_fw[mat][row * 4 + 3] = e3 * inv;
}

// ---------------- support = X @ gcn_w ----------------
__global__ void __launch_bounds__(256) k_support(const float* __restrict__ X,
                                                 const float* __restrict__ W) {
    __shared__ float Xs[32][WIN];
    int tid = threadIdx.x;
    int row0 = blockIdx.x * 32;
    const float4* Xg = (const float4*)(X + (size_t)row0 * WIN);
    float4* Xs4 = (float4*)&Xs[0][0];
    #pragma unroll
    for (int j = 0; j < (32 * WIN / 4) / 256; j++)
        Xs4[tid + j * 256] = Xg[tid + j * 256];
    __syncthreads();
    int f = tid & 127, ty = tid >> 7;
    float acc[16];
    #pragma unroll
    for (int r = 0; r < 16; r++) acc[r] = 0.f;
    for (int k = 0; k < WIN; k++) {
        float w = W[k * F + f];
        #pragma unroll
        for (int r = 0; r < 16; r++)
            acc[r] = fmaf(Xs[ty * 16 + r][k], w, acc[r]);
    }
    #pragma unroll
    for (int r = 0; r < 16; r++)
        g_support[(size_t)(row0 + ty * 16 + r) * F + f] = acc[r];
}

// ---------------- premix: raw A -> 12 fragment-ordered tf32 planes + v1 ----------------
// grid: 128 blocks (16-row bands), 256 threads.
__global__ void __launch_bounds__(256) k_premix_f(const float* __restrict__ A) {
    __shared__ float As[4][16][132];     // raw edge data, padded
    __shared__ float wsm[48];
    __shared__ float rawsum[4][16];      // raw rowsums per edge
    const int tid = threadIdx.x, lane = tid & 31, warp = tid >> 5;
    const int g = lane >> 2, cl = lane & 3;
    const int n0 = blockIdx.x * 16;

    if (tid < 48) wsm[tid] = ((const float*)g_fw)[tid];
    // raw rowsum accumulator: thread owns (e = tid>>6, r = (tid>>2)&15) when (tid&3)==0
    float racc = 0.f;
    __syncthreads();

    for (int chunk = 0; chunk < 16; chunk++) {
        const int m0 = chunk * 128;
        #pragma unroll
        for (int e = 0; e < 4; e++)
            #pragma unroll
            for (int j = 0; j < 2; j++) {
                int idx = tid + j * 256;            // 0..511
                int r = idx >> 5, m4 = idx & 31;
                *(float4*)&As[e][r][m4 * 4] =
                    *(const float4*)(A + (size_t)e * NNSZ + (size_t)(n0 + r) * N + m0 + m4 * 4);
            }
        __syncthreads();

        // raw rowsums of this chunk
        {
            int e = tid >> 6, r = (tid >> 2) & 15, part = tid & 3;
            float s = 0.f;
            #pragma unroll
            for (int i = 0; i < 32; i++) s += As[e][r][part * 32 + i];
            s += __shfl_xor_sync(0xffffffffu, s, 1);
            s += __shfl_xor_sync(0xffffffffu, s, 2);
            if (part == 0) racc += s;
        }

        // 12 planes x 16 k8-units -> 192 warp tasks
        for (int task = warp; task < 192; task += 8) {
            int plane = task >> 4, ktl = task & 15;
            int s = plane >> 2;
            const float* wv = wsm + (2 - s) * 16 + (plane & 3) * 4;
            int col = ktl * 8 + cl;
            float v0 = 0.f, v1 = 0.f, v2 = 0.f, v3 = 0.f;
            #pragma unroll
            for (int e = 0; e < 4; e++) {
                float we = wv[e];
                v0 = fmaf(we, As[e][g][col], v0);
                v1 = fmaf(we, As[e][g + 8][col], v1);
                v2 = fmaf(we, As[e][g][col + 4], v2);
                v3 = fmaf(we, As[e][g + 8][col + 4], v3);
            }
            float4 o = make_float4(to_tf32(v0), to_tf32(v1), to_tf32(v2), to_tf32(v3));
            size_t unit = (size_t)blockIdx.x * 256 + chunk * 16 + ktl;
            *(float4*)(g_Am + (size_t)plane * NNSZ + unit * 128 + lane * 4) = o;
        }
        __syncthreads();
    }

    // publish raw rowsums, mix with fw3 -> v1
    if ((tid & 3) == 0) rawsum[tid >> 6][(tid >> 2) & 15] = racc;
    __syncthreads();
    if (tid < 64) {
        int c = tid & 3, r = tid >> 2;
        const float* w3v = wsm + 2 * 16 + c * 4;
        g_v1[c * N + n0 + r] = w3v[0] * rawsum[0][r] + w3v[1] * rawsum[1][r]
                             + w3v[2] * rawsum[2][r] + w3v[3] * rawsum[3][r];
    }
}

// ---------------- matvec on raw A: vout_c = sum_i w[c,i] * (A_i @ vin_c) ----------------
__global__ void __launch_bounds__(256) k_matvec(const float* __restrict__ A, int stage) {
    const float* __restrict__ vin = (stage == 0) ? g_v1 : g_v2;
    float* __restrict__ vout = (stage == 0) ? g_v2 : g_v3;
    const float* wsrc = (stage == 0) ? g_fw[1] : g_fw[0];
    int n = blockIdx.x;
    int tid = threadIdx.x;
    float w[16];
    #pragma unroll
    for (int j = 0; j < 16; j++) w[j] = wsrc[j];
    float acc0 = 0.f, acc1 = 0.f, acc2 = 0.f, acc3 = 0.f;
    #pragma unroll
    for (int it = 0; it < (N / 4) / 256; it++) {
        int m4 = tid + it * 256;
        float4 vv0 = ((const float4*)(vin + 0 * N))[m4];
        float4 vv1 = ((const float4*)(vin + 1 * N))[m4];
        float4 vv2 = ((const float4*)(vin + 2 * N))[m4];
        float4 vv3 = ((const float4*)(vin + 3 * N))[m4];
        #pragma unroll
        for (int i = 0; i < 4; i++) {
            float4 a = ((const float4*)(A + (size_t)i * NNSZ + (size_t)n * N))[m4];
            float d0 = a.x * vv0.x + a.y * vv0.y + a.z * vv0.z + a.w * vv0.w;
            float d1 = a.x * vv1.x + a.y * vv1.y + a.z * vv1.z + a.w * vv1.w;
            float d2 = a.x * vv2.x + a.y * vv2.y + a.z * vv2.z + a.w * vv2.w;
            float d3 = a.x * vv3.x + a.y * vv3.y + a.z * vv3.z + a.w * vv3.w;
            acc0 = fmaf(w[0 * 4 + i], d0, acc0);
            acc1 = fmaf(w[1 * 4 + i], d1, acc1);
            acc2 = fmaf(w[2 * 4 + i], d2, acc2);
            acc3 = fmaf(w[3 * 4 + i], d3, acc3);
        }
    }
    #pragma unroll
    for (int off = 16; off > 0; off >>= 1) {
        acc0 += __shfl_down_sync(0xffffffffu, acc0, off);
        acc1 += __shfl_down_sync(0xffffffffu, acc1, off);
        acc2 += __shfl_down_sync(0xffffffffu, acc2, off);
        acc3 += __shfl_down_sync(0xffffffffu, acc3, off);
    }
    __shared__ float red[8][4];
    int lane = tid & 31, wid = tid >> 5;
    if (lane == 0) { red[wid][0] = acc0; red[wid][1] = acc1; red[wid][2] = acc2; red[wid][3] = acc3; }
    __syncthreads();
    if (tid < 4) {
        float s = 0.f;
        #pragma unroll
        for (int wv = 0; wv < 8; wv++) s += red[wv][tid];
        vout[tid * N + n] = s;
    }
}

// ---------------- d, Sp natural, SpB fragment-order ----------------
// grid: 256 blocks (8-node groups), 256 threads
__global__ void __launch_bounds__(256) k_dSp_f() {
    __shared__ float sup[8][132];
    __shared__ float dsm[4][8];
    const int tid = threadIdx.x;
    const int k0 = blockIdx.x * 8;
    {
        int r = tid >> 5, f4 = (tid & 31) * 4;
        *(float4*)&sup[r][f4] = *(const float4*)(g_support + (size_t)(k0 + r) * F + f4);
    }
    if (tid < 32) {
        int c = tid >> 3, kk = tid & 7;
        float deg = g_v3[c * N + k0 + kk] + 1.0f;
        float d = (deg > 0.f) ? rsqrtf(deg) : 0.f;
        dsm[c][kk] = d;
        g_d[c * N + k0 + kk] = d;
    }
    __syncthreads();
    {   // natural Sp
        int r = tid >> 5, f4 = (tid & 31) * 4;
        float4 s = *(float4*)&sup[r][f4];
        #pragma unroll
        for (int c = 0; c < 4; c++) {
            float d = dsm[c][r];
            float4 o = make_float4(d * s.x, d * s.y, d * s.z, d * s.w);
            *(float4*)(g_Sp + ((size_t)c * N + k0 + r) * F + f4) = o;
        }
    }
    {   // fragment-order SpB: unit = this k8 x n16(nt)
        int nt = tid >> 5, l = tid & 31;
        int kl = l & 3, nl = nt * 16 + (l >> 2);
        #pragma unroll
        for (int c = 0; c < 4; c++) {
            float4 o;
            o.x = to_tf32(dsm[c][kl]     * sup[kl][nl]);
            o.y = to_tf32(dsm[c][kl + 4] * sup[kl + 4][nl]);
            o.z = to_tf32(dsm[c][kl]     * sup[kl][nl + 8]);
            o.w = to_tf32(dsm[c][kl + 4] * sup[kl + 4][nl + 8]);
            *(float4*)(g_SpB + (size_t)c * NFSZ + ((size_t)blockIdx.x * 8 + nt) * 128 + l * 4) = o;
        }
    }
}

// ---------------- main GEMM: fragment-order direct-LDG mma tf32 ----------------
// D[64 node x 128 f] per CTA; grid (32, 4); 256 threads; warp tile 32x32.
// A plane: unit(m16,k8) at (mt*256+kt)*128 ; B plane: unit(k8,n16) at (kt*8+nt)*128.
__global__ void __launch_bounds__(256) k_gemm_f(const float* __restrict__ bias,
                                                float* __restrict__ out, int stage) {
    __shared__ float sm[64][132];
    const int tid = threadIdx.x, lane = tid & 31, warp = tid >> 5;
    const int wm = warp >> 2, wn = warp & 3;       // 2 x 4 warps
    const int c = blockIdx.y;
    const int n0 = blockIdx.x * 64;

    const float* __restrict__ Af = g_Am + (size_t)(stage * 4 + c) * NNSZ;
    const float* __restrict__ Bfp = ((stage == 0) ? g_SpB : (stage == 1) ? g_T0B : g_T1B)
                                    + (size_t)c * NFSZ;
    // uint4 bases (unit = 32 uint4)
    const uint4* __restrict__ Abase = (const uint4*)Af
        + ((size_t)(blockIdx.x * 4 + wm * 2) * 256) * 32 + lane;
    const uint4* __restrict__ Bbase = (const uint4*)Bfp + (size_t)(wn * 2) * 32 + lane;

    float acc[2][4][4];
    #pragma unroll
    for (int i = 0; i < 2; i++)
        #pragma unroll
        for (int j = 0; j < 4; j++)
            #pragma unroll
            for (int q = 0; q < 4; q++) acc[i][j][q] = 0.f;

    uint4 ab[4][2], bb[4][2];
    #pragma unroll
    for (int p = 0; p < 3; p++) {
        ab[p][0] = Abase[(size_t)p * 32];
        ab[p][1] = Abase[(size_t)256 * 32 + (size_t)p * 32];
        bb[p][0] = Bbase[(size_t)p * 256];
        bb[p][1] = Bbase[(size_t)p * 256 + 32];
    }

    for (int kt4 = 0; kt4 < 64; kt4++) {
        #pragma unroll
        for (int s = 0; s < 4; s++) {
            const int kt = kt4 * 4 + s;
            const int slot = kt & 3;
            const int pf = kt + 3;
            if (pf < 256) {
                const int ps = pf & 3;
                ab[ps][0] = Abase[(size_t)pf * 32];
                ab[ps][1] = Abase[(size_t)256 * 32 + (size_t)pf * 32];
                bb[ps][0] = Bbase[(size_t)pf * 256];
                bb[ps][1] = Bbase[(size_t)pf * 256 + 32];
            }
            #pragma unroll
            for (int i = 0; i < 2; i++) {
                uint4 a = ab[slot][i];
                #pragma unroll
                for (int u = 0; u < 2; u++) {
                    uint4 b = bb[slot][u];
                    mma_tf32(acc[i][u * 2][0], acc[i][u * 2][1], acc[i][u * 2][2], acc[i][u * 2][3],
                             a.x, a.y, a.z, a.w, b.x, b.y);
                    mma_tf32(acc[i][u * 2 + 1][0], acc[i][u * 2 + 1][1], acc[i][u * 2 + 1][2], acc[i][u * 2 + 1][3],
                             a.x, a.y, a.z, a.w, b.z, b.w);
                }
            }
        }
    }

    // park D in smem (natural [node][f])
    {
        const int g = lane >> 2, th = lane & 3;
        #pragma unroll
        for (int i = 0; i < 2; i++)
            #pragma unroll
            for (int j = 0; j < 4; j++) {
                int row = wm * 32 + i * 16 + g;
                int col = wn * 32 + (j >> 1) * 16 + (j & 1) * 8 + 2 * th;
                sm[row][col] = acc[i][j][0];
                sm[row][col + 1] = acc[i][j][1];
                sm[row + 8][col] = acc[i][j][2];
                sm[row + 8][col + 1] = acc[i][j][3];
            }
    }
    __syncthreads();

    if (stage < 2) {
        // write next stage's B plane in fragment order (tf32-rounded)
        float* __restrict__ Bout = ((stage == 0) ? g_T0B : g_T1B) + (size_t)c * NFSZ;
        const int ka = warp * 8 + (lane & 3);       // local node row base
        const int nloc = lane >> 2;
        #pragma unroll
        for (int q = 0; q < 8; q++) {
            int nl = q * 16 + nloc;
            float4 o;
            o.x = to_tf32(sm[ka][nl]);
            o.y = to_tf32(sm[ka + 4][nl]);
            o.z = to_tf32(sm[ka][nl + 8]);
            o.w = to_tf32(sm[ka + 4][nl + 8]);
            *(float4*)(Bout + ((size_t)(blockIdx.x * 8 + warp) * 8 + q) * 128 + lane * 4) = o;
        }
    } else {
        const int r = tid >> 2;
        const int fc = (tid & 3) * 32;
        const int node = n0 + r;
        const float dd = g_d[c * N + node];
        const float* sp = g_Sp + ((size_t)(c * N + node)) * F;
        float* op = out + (size_t)node * (C * F) + c * F;
        #pragma unroll
        for (int j0 = 0; j0 < 32; j0 += 4) {
            float4 a4 = *(float4*)&sm[r][fc + j0];
            float4 s4 = *(const float4*)(sp + fc + j0);
            float4 b4 = *(const float4*)(bias + fc + j0);
            float4 o;
            o.x = fmaxf(dd * (a4.x + s4.x) + b4.x, 0.f);
            o.y = fmaxf(dd * (a4.y + s4.y) + b4.y, 0.f);
            o.z = fmaxf(dd * (a4.z + s4.z) + b4.z, 0.f);
            o.w = fmaxf(dd * (a4.w + s4.w) + b4.w, 0.f);
            *(float4*)(op + fc + j0) = o;
        }
    }
}

// ---------------- launcher ----------------
extern "C" void kernel_launch(void* const* d_in, const int* in_sizes, int n_in,
                              void* d_out, int out_size) {
    const float* A  = (const float*)d_in[0];   // [E,N,N]
    const float* X  = (const float*)d_in[1];   // [N,WIN]
    const float* w1 = (const float*)d_in[2];   // [C,E]
    const float* w2 = (const float*)d_in[3];   // [C,E]
    const float* w3 = (const float*)d_in[4];   // [C,C]
    const float* gw = (const float*)d_in[5];   // [WIN,F]
    const float* gb = (const float*)d_in[6];   // [F]
    float* out = (float*)d_out;                // [N, C*F]

    k_softmax<<<1, 32>>>(w1, w2, w3);
    k_support<<<N / 32, 256>>>(X, gw);
    k_premix_f<<<128, 256>>>(A);                 // 12 frag-order planes + v1
    k_matvec<<<N, 256>>>(A, 0);                  // v2 = Hb @ v1
    k_matvec<<<N, 256>>>(A, 1);                  // v3 = Ha @ v2
    k_dSp_f<<<N / 8, 256>>>();                   // d, Sp natural, SpB frag
    k_gemm_f<<<dim3(N / 64, C), 256>>>(gb, out, 0);   // T0B = (Hc @ Sp) frag
    k_gemm_f<<<dim3(N / 64, C), 256>>>(gb, out, 1);   // T1B = (Hb @ T0) frag
    k_gemm_f<<<dim3(N / 64, C), 256>>>(gb, out, 2);   // out = relu(d*(Ha@T1+Sp)+b)
}

// round 6
// speedup vs baseline: 2.1232x; 1.1594x over previous
#include <cuda_runtime.h>
#include <cstdint>

#define N 2048
#define E 4
#define C 4
#define F 128      // W_OUT
#define WIN 256
#define NNSZ ((size_t)N * N)
#define NFSZ ((size_t)N * F)

// ---------------- scratch (static device globals; no allocation) ----------------
__device__ float g_fw[3][16];            // softmaxed weights: [0]=fw1, [1]=fw2, [2]=fw3
__device__ float g_support[N * F];       // X @ gcn_w              [n][f]
__device__ float g_part[16 * E * N];     // per-chunk partial raw rowsums
__device__ float g_v1[C * N];
__device__ float g_v2[C * N];
__device__ float g_v3[C * N];
__device__ float g_d[C * N];             // deg^-1/2
__device__ float g_Sp[C * N * F];        // diag(d)@support natural [c][n][f]
__device__ float g_SpB[C * N * F];       // fragment-order B plane (stage 0)
__device__ float g_T0B[C * N * F];       // fragment-order B plane (stage 1)
__device__ float g_T1B[C * N * F];       // fragment-order B plane (stage 2)
// fragment-ordered premixed adjacency planes: [stage*4 + c], unit = m16 x k8 (128 floats)
__device__ float g_Am[12 * NNSZ];

__device__ __forceinline__ float to_tf32(float x) {
    float r; asm("cvt.rna.tf32.f32 %0, %1;" : "=f"(r) : "f"(x)); return r;
}

__device__ __forceinline__ void mma_tf32(float& d0, float& d1, float& d2, float& d3,
                                         uint32_t a0, uint32_t a1, uint32_t a2, uint32_t a3,
                                         uint32_t b0, uint32_t b1) {
    asm volatile(
        "mma.sync.aligned.m16n8k8.row.col.f32.tf32.tf32.f32 "
        "{%0,%1,%2,%3}, {%4,%5,%6,%7}, {%8,%9}, {%0,%1,%2,%3};"
        : "+f"(d0), "+f"(d1), "+f"(d2), "+f"(d3)
        : "r"(a0), "r"(a1), "r"(a2), "r"(a3), "r"(b0), "r"(b1));
}

// ---------------- tiny: softmax of 4x4 weight rows ----------------
__global__ void k_softmax(const float* __restrict__ w1,
                          const float* __restrict__ w2,
                          const float* __restrict__ w3) {
    int t = threadIdx.x;
    if (t >= 12) return;
    int mat = t >> 2, row = t & 3;
    const float* src = (mat == 0) ? w1 : (mat == 1) ? w2 : w3;
    float a0 = src[row * 4 + 0], a1 = src[row * 4 + 1];
    float a2 = src[row * 4 + 2], a3 = src[row * 4 + 3];
    float mx = fmaxf(fmaxf(a0, a1), fmaxf(a2, a3));
    float e0 = expf(a0 - mx), e1 = expf(a1 - mx), e2 = expf(a2 - mx), e3 = expf(a3 - mx);
    float inv = 1.0f / (e0 + e1 + e2 + e3);
    g_fw[mat][row * 4 + 0] = e0 * inv;
    g_fw[mat][row * 4 + 1] = e1 * inv;
    g_fw[mat][row * 4 + 2] = e2 * inv;
    g_fw[mat][row * 4 + 3] = e3 * inv;
}

// ---------------- support = X @ gcn_w ----------------
__global__ void __launch_bounds__(256) k_support(const float* __restrict__ X,
                                                 const float* __restrict__ W) {
    __shared__ float Xs[32][WIN];
    int tid = threadIdx.x;
    int row0 = blockIdx.x * 32;
    const float4* Xg = (const float4*)(X + (size_t)row0 * WIN);
    float4* Xs4 = (float4*)&Xs[0][0];
    #pragma unroll
    for (int j = 0; j < (32 * WIN / 4) / 256; j++)
        Xs4[tid + j * 256] = Xg[tid + j * 256];
    __syncthreads();
    int f = tid & 127, ty = tid >> 7;
    float acc[16];
    #pragma unroll
    for (int r = 0; r < 16; r++) acc[r] = 0.f;
    for (int k = 0; k < WIN; k++) {
        float w = W[k * F + f];
        #pragma unroll
        for (int r = 0; r < 16; r++)
            acc[r] = fmaf(Xs[ty * 16 + r][k], w, acc[r]);
    }
    #pragma unroll
    for (int r = 0; r < 16; r++)
        g_support[(size_t)(row0 + ty * 16 + r) * F + f] = acc[r];
}

// ---------------- premix: one (band, chunk) tile per CTA ----------------
// grid: (16 chunks, 128 bands), 256 threads. Writes 12 frag-order planes + partial rowsums.
__global__ void __launch_bounds__(256) k_premix_f(const float* __restrict__ A) {
    __shared__ float As[4][16][132];
    __shared__ float wsm[48];
    const int tid = threadIdx.x, lane = tid & 31, warp = tid >> 5;
    const int g = lane >> 2, cl = lane & 3;
    const int ch = blockIdx.x;            // 0..15 (128-col chunk)
    const int band = blockIdx.y;          // 0..127 (16-row band)
    const int n0 = band * 16, m0 = ch * 128;

    if (tid < 48) wsm[tid] = ((const float*)g_fw)[tid];
    #pragma unroll
    for (int e = 0; e < 4; e++)
        #pragma unroll
        for (int j = 0; j < 2; j++) {
            int idx = tid + j * 256;
            int r = idx >> 5, m4 = idx & 31;
            *(float4*)&As[e][r][m4 * 4] =
                *(const float4*)(A + (size_t)e * NNSZ + (size_t)(n0 + r) * N + m0 + m4 * 4);
        }
    __syncthreads();

    // raw partial rowsums -> g_part[ch][e][n]
    {
        int e = tid >> 6, r = (tid >> 2) & 15, part = tid & 3;
        float s = 0.f;
        #pragma unroll
        for (int i = 0; i < 32; i++) s += As[e][r][part * 32 + i];
        s += __shfl_xor_sync(0xffffffffu, s, 1);
        s += __shfl_xor_sync(0xffffffffu, s, 2);
        if (part == 0) g_part[(size_t)ch * (4 * N) + e * N + n0 + r] = s;
    }

    // 12 planes x 16 k8-units = 192 warp tasks
    for (int task = warp; task < 192; task += 8) {
        int plane = task >> 4, ktl = task & 15;
        int s = plane >> 2;
        const float* wv = wsm + (2 - s) * 16 + (plane & 3) * 4;
        int col = ktl * 8 + cl;
        float v0 = 0.f, v1 = 0.f, v2 = 0.f, v3 = 0.f;
        #pragma unroll
        for (int e = 0; e < 4; e++) {
            float we = wv[e];
            v0 = fmaf(we, As[e][g][col], v0);
            v1 = fmaf(we, As[e][g + 8][col], v1);
            v2 = fmaf(we, As[e][g][col + 4], v2);
            v3 = fmaf(we, As[e][g + 8][col + 4], v3);
        }
        float4 o = make_float4(to_tf32(v0), to_tf32(v1), to_tf32(v2), to_tf32(v3));
        size_t unit = (size_t)band * 256 + ch * 16 + ktl;
        *(float4*)(g_Am + (size_t)plane * NNSZ + unit * 128 + lane * 4) = o;
    }
}

// ---------------- reduce partials, mix with fw3 -> v1 ----------------
__global__ void k_mix_v1() {
    int n = blockIdx.x * 256 + threadIdx.x;
    if (n >= N) return;
    float rs[4];
    #pragma unroll
    for (int e = 0; e < 4; e++) {
        float s = 0.f;
        #pragma unroll
        for (int ch = 0; ch < 16; ch++)
            s += g_part[(size_t)ch * (4 * N) + e * N + n];
        rs[e] = s;
    }
    #pragma unroll
    for (int c = 0; c < 4; c++)
        g_v1[c * N + n] = g_fw[2][c * 4 + 0] * rs[0] + g_fw[2][c * 4 + 1] * rs[1]
                        + g_fw[2][c * 4 + 2] * rs[2] + g_fw[2][c * 4 + 3] * rs[3];
}

// ---------------- matvec on raw A: vout_c = sum_i w[c,i] * (A_i @ vin_c) ----------------
__global__ void __launch_bounds__(256) k_matvec(const float* __restrict__ A, int stage) {
    const float* __restrict__ vin = (stage == 0) ? g_v1 : g_v2;
    float* __restrict__ vout = (stage == 0) ? g_v2 : g_v3;
    const float* wsrc = (stage == 0) ? g_fw[1] : g_fw[0];
    int n = blockIdx.x;
    int tid = threadIdx.x;
    float w[16];
    #pragma unroll
    for (int j = 0; j < 16; j++) w[j] = wsrc[j];
    float acc0 = 0.f, acc1 = 0.f, acc2 = 0.f, acc3 = 0.f;
    #pragma unroll
    for (int it = 0; it < (N / 4) / 256; it++) {
        int m4 = tid + it * 256;
        float4 vv0 = ((const float4*)(vin + 0 * N))[m4];
        float4 vv1 = ((const float4*)(vin + 1 * N))[m4];
        float4 vv2 = ((const float4*)(vin + 2 * N))[m4];
        float4 vv3 = ((const float4*)(vin + 3 * N))[m4];
        #pragma unroll
        for (int i = 0; i < 4; i++) {
            float4 a = ((const float4*)(A + (size_t)i * NNSZ + (size_t)n * N))[m4];
            float d0 = a.x * vv0.x + a.y * vv0.y + a.z * vv0.z + a.w * vv0.w;
            float d1 = a.x * vv1.x + a.y * vv1.y + a.z * vv1.z + a.w * vv1.w;
            float d2 = a.x * vv2.x + a.y * vv2.y + a.z * vv2.z + a.w * vv2.w;
            float d3 = a.x * vv3.x + a.y * vv3.y + a.z * vv3.z + a.w * vv3.w;
            acc0 = fmaf(w[0 * 4 + i], d0, acc0);
            acc1 = fmaf(w[1 * 4 + i], d1, acc1);
            acc2 = fmaf(w[2 * 4 + i], d2, acc2);
            acc3 = fmaf(w[3 * 4 + i], d3, acc3);
        }
    }
    #pragma unroll
    for (int off = 16; off > 0; off >>= 1) {
        acc0 += __shfl_down_sync(0xffffffffu, acc0, off);
        acc1 += __shfl_down_sync(0xffffffffu, acc1, off);
        acc2 += __shfl_down_sync(0xffffffffu, acc2, off);
        acc3 += __shfl_down_sync(0xffffffffu, acc3, off);
    }
    __shared__ float red[8][4];
    int lane = tid & 31, wid = tid >> 5;
    if (lane == 0) { red[wid][0] = acc0; red[wid][1] = acc1; red[wid][2] = acc2; red[wid][3] = acc3; }
    __syncthreads();
    if (tid < 4) {
        float s = 0.f;
        #pragma unroll
        for (int wv = 0; wv < 8; wv++) s += red[wv][tid];
        vout[tid * N + n] = s;
    }
}

// ---------------- d, Sp natural, SpB fragment-order ----------------
__global__ void __launch_bounds__(256) k_dSp_f() {
    __shared__ float sup[8][132];
    __shared__ float dsm[4][8];
    const int tid = threadIdx.x;
    const int k0 = blockIdx.x * 8;
    {
        int r = tid >> 5, f4 = (tid & 31) * 4;
        *(float4*)&sup[r][f4] = *(const float4*)(g_support + (size_t)(k0 + r) * F + f4);
    }
    if (tid < 32) {
        int c = tid >> 3, kk = tid & 7;
        float deg = g_v3[c * N + k0 + kk] + 1.0f;
        float d = (deg > 0.f) ? rsqrtf(deg) : 0.f;
        dsm[c][kk] = d;
        g_d[c * N + k0 + kk] = d;
    }
    __syncthreads();
    {
        int r = tid >> 5, f4 = (tid & 31) * 4;
        float4 s = *(float4*)&sup[r][f4];
        #pragma unroll
        for (int c = 0; c < 4; c++) {
            float d = dsm[c][r];
            float4 o = make_float4(d * s.x, d * s.y, d * s.z, d * s.w);
            *(float4*)(g_Sp + ((size_t)c * N + k0 + r) * F + f4) = o;
        }
    }
    {
        int nt = tid >> 5, l = tid & 31;
        int kl = l & 3, nl = nt * 16 + (l >> 2);
        #pragma unroll
        for (int c = 0; c < 4; c++) {
            float4 o;
            o.x = to_tf32(dsm[c][kl]     * sup[kl][nl]);
            o.y = to_tf32(dsm[c][kl + 4] * sup[kl + 4][nl]);
            o.z = to_tf32(dsm[c][kl]     * sup[kl][nl + 8]);
            o.w = to_tf32(dsm[c][kl + 4] * sup[kl + 4][nl + 8]);
            *(float4*)(g_SpB + (size_t)c * NFSZ + ((size_t)blockIdx.x * 8 + nt) * 128 + l * 4) = o;
        }
    }
}

// ---------------- main GEMM: 512 threads, warp tile 16x32, direct-LDG mma tf32 ----------------
__global__ void __launch_bounds__(512) k_gemm_f(const float* __restrict__ bias,
                                                float* __restrict__ out, int stage) {
    __shared__ float sm[64][132];
    const int tid = threadIdx.x, lane = tid & 31, warp = tid >> 5;   // 16 warps
    const int wm = warp >> 2, wn = warp & 3;       // 4 x 4
    const int c = blockIdx.y;
    const int n0 = blockIdx.x * 64;

    const float* __restrict__ Af = g_Am + (size_t)(stage * 4 + c) * NNSZ;
    const float* __restrict__ Bfp = ((stage == 0) ? g_SpB : (stage == 1) ? g_T0B : g_T1B)
                                    + (size_t)c * NFSZ;
    const uint4* __restrict__ Abase = (const uint4*)Af
        + ((size_t)(blockIdx.x * 4 + wm) * 256) * 32 + lane;
    const uint4* __restrict__ Bbase = (const uint4*)Bfp + (size_t)(wn * 2) * 32 + lane;

    float acc[4][4];
    #pragma unroll
    for (int j = 0; j < 4; j++)
        #pragma unroll
        for (int q = 0; q < 4; q++) acc[j][q] = 0.f;

    uint4 ab[4], bb[4][2];
    #pragma unroll
    for (int p = 0; p < 3; p++) {
        ab[p] = Abase[(size_t)p * 32];
        bb[p][0] = Bbase[(size_t)p * 256];
        bb[p][1] = Bbase[(size_t)p * 256 + 32];
    }

    for (int kt4 = 0; kt4 < 64; kt4++) {
        #pragma unroll
        for (int s = 0; s < 4; s++) {
            const int kt = kt4 * 4 + s;
            const int slot = kt & 3;
            const int pf = kt + 3;
            if (pf < 256) {
                const int ps = pf & 3;
                ab[ps] = Abase[(size_t)pf * 32];
                bb[ps][0] = Bbase[(size_t)pf * 256];
                bb[ps][1] = Bbase[(size_t)pf * 256 + 32];
            }
            uint4 a = ab[slot];
            #pragma unroll
            for (int u = 0; u < 2; u++) {
                uint4 b = bb[slot][u];
                mma_tf32(acc[u * 2][0], acc[u * 2][1], acc[u * 2][2], acc[u * 2][3],
                         a.x, a.y, a.z, a.w, b.x, b.y);
                mma_tf32(acc[u * 2 + 1][0], acc[u * 2 + 1][1], acc[u * 2 + 1][2], acc[u * 2 + 1][3],
                         a.x, a.y, a.z, a.w, b.z, b.w);
            }
        }
    }

    // park D in smem (natural [node][f])
    {
        const int g = lane >> 2, th = lane & 3;
        #pragma unroll
        for (int j = 0; j < 4; j++) {
            int row = wm * 16 + g;
            int col = wn * 32 + (j >> 1) * 16 + (j & 1) * 8 + 2 * th;
            sm[row][col] = acc[j][0];
            sm[row][col + 1] = acc[j][1];
            sm[row + 8][col] = acc[j][2];
            sm[row + 8][col + 1] = acc[j][3];
        }
    }
    __syncthreads();

    if (stage < 2) {
        float* __restrict__ Bout = ((stage == 0) ? g_T0B : g_T1B) + (size_t)c * NFSZ;
        const int ku = warp >> 1;                  // 0..7
        const int nu0 = (warp & 1) * 4;
        const int ka = ku * 8 + (lane & 3);
        const int nloc = lane >> 2;
        #pragma unroll
        for (int q = 0; q < 4; q++) {
            int nu = nu0 + q;
            int nl = nu * 16 + nloc;
            float4 o;
            o.x = to_tf32(sm[ka][nl]);
            o.y = to_tf32(sm[ka + 4][nl]);
            o.z = to_tf32(sm[ka][nl + 8]);
            o.w = to_tf32(sm[ka + 4][nl + 8]);
            *(float4*)(Bout + ((size_t)(blockIdx.x * 8 + ku) * 8 + nu) * 128 + lane * 4) = o;
        }
    } else {
        const int r = tid >> 3;
        const int fc = (tid & 7) * 16;
        const int node = n0 + r;
        const float dd = g_d[c * N + node];
        const float* sp = g_Sp + ((size_t)(c * N + node)) * F;
        float* op = out + (size_t)node * (C * F) + c * F;
        #pragma unroll
        for (int j0 = 0; j0 < 16; j0 += 4) {
            float4 a4 = *(float4*)&sm[r][fc + j0];
            float4 s4 = *(const float4*)(sp + fc + j0);
            float4 b4 = *(const float4*)(bias + fc + j0);
            float4 o;
            o.x = fmaxf(dd * (a4.x + s4.x) + b4.x, 0.f);
            o.y = fmaxf(dd * (a4.y + s4.y) + b4.y, 0.f);
            o.z = fmaxf(dd * (a4.z + s4.z) + b4.z, 0.f);
            o.w = fmaxf(dd * (a4.w + s4.w) + b4.w, 0.f);
            *(float4*)(op + fc + j0) = o;
        }
    }
}

// ---------------- launcher ----------------
extern "C" void kernel_launch(void* const* d_in, const int* in_sizes, int n_in,
                              void* d_out, int out_size) {
    const float* A  = (const float*)d_in[0];   // [E,N,N]
    const float* X  = (const float*)d_in[1];   // [N,WIN]
    const float* w1 = (const float*)d_in[2];   // [C,E]
    const float* w2 = (const float*)d_in[3];   // [C,E]
    const float* w3 = (const float*)d_in[4];   // [C,C]
    const float* gw = (const float*)d_in[5];   // [WIN,F]
    const float* gb = (const float*)d_in[6];   // [F]
    float* out = (float*)d_out;                // [N, C*F]

    k_softmax<<<1, 32>>>(w1, w2, w3);
    k_support<<<N / 32, 256>>>(X, gw);
    k_premix_f<<<dim3(16, 128), 256>>>(A);       // 12 frag planes + partial rowsums
    k_mix_v1<<<N / 256, 256>>>();                // v1
    k_matvec<<<N, 256>>>(A, 0);                  // v2 = Hb @ v1
    k_matvec<<<N, 256>>>(A, 1);                  // v3 = Ha @ v2
    k_dSp_f<<<N / 8, 256>>>();                   // d, Sp natural, SpB frag
    k_gemm_f<<<dim3(N / 64, C), 512>>>(gb, out, 0);   // T0B
    k_gemm_f<<<dim3(N / 64, C), 512>>>(gb, out, 1);   // T1B
    k_gemm_f<<<dim3(N / 64, C), 512>>>(gb, out, 2);   // out
}